// round 7
// baseline (speedup 1.0000x reference)
#include <cuda_runtime.h>
#include <cstdint>

// Problem shape (fixed by the dataset)
#define BB 4
#define NN 4096
#define DD 4096
#define EE 64
#define BN (BB * NN)

// ---- scratch (no allocations allowed) ----
__device__ float          g_probsT[BB][EE][NN];   // 4 MB: probs transposed [b][e][n]
__device__ unsigned short g_sorted[BB][EE][NN];   // 2 MB: per (b,e) token order, descending prob

// ============================================================================
// Kernel 1: router GEMM (fp32 via packed fma.rn.f32x2) + fused softmax.
// grid 256 CTAs x 256 threads; each CTA: 64 tokens x all 64 experts, K=4096.
// W stored DUPLICATED in smem so each expert loads as an LDS.64 {w,w} pair —
// no dup-movs in the inner loop: per k = 2 LDS64(x) + 4 LDS64(w) + 8 FFMA2.
// Two-level accumulation (per-32k tile folded into main) keeps fp32 noise
// ~8e-7 so the greedy ranking matches the reference.
// ============================================================================
__global__ void __launch_bounds__(256, 2) k_router_gemm(const float* __restrict__ x,
                                                        const float* __restrict__ W)
{
    // phase A: xs[32][66] (2112 f) + ws2[32][130] (4160 f) = 6272 floats (24.5KB)
    // phase B: ls[64][65] = 4160 floats (reuses su)
    __shared__ __align__(16) float su[6272];
    float (*xs)[66]   = reinterpret_cast<float (*)[66]>(su);           // [k][tok], stride even -> LDS64 ok
    float (*ws2)[130] = reinterpret_cast<float (*)[130]>(su + 2112);   // [k][2e] duplicated experts
    float (*ls)[65]   = reinterpret_cast<float (*)[65]>(su);           // logits/probs [tok][e]
    __shared__ float sinv[64];

    const int tid = threadIdx.x;
    const int tt  = tid & 15;   // token-pair group: pairs at tokens 2*tt + 32*i (i=0,1)
    const int te  = tid >> 4;   // expert group: experts te*4 .. te*4+3
    const int m0  = blockIdx.x * 64;

    unsigned long long accm[2][4] = {};  // [pair i][expert j], f32x2 packed

    for (int kt = 0; kt < DD / 32; ++kt) {
        __syncthreads();
        // x tile: 64 tok x 32 k (float4 along k, transposed scalar stores)
        #pragma unroll
        for (int it = 0; it < 2; ++it) {
            int f = tid + it * 256;
            int r = f >> 3, c4 = f & 7;
            float4 v = __ldcs(reinterpret_cast<const float4*>(
                x + (size_t)(m0 + r) * DD + kt * 32 + c4 * 4));
            xs[c4 * 4 + 0][r] = v.x; xs[c4 * 4 + 1][r] = v.y;
            xs[c4 * 4 + 2][r] = v.z; xs[c4 * 4 + 3][r] = v.w;
        }
        // W tile: 64 e x 32 k, stored duplicated ({w,w} adjacent)
        #pragma unroll
        for (int it = 0; it < 2; ++it) {
            int f = tid + it * 256;
            int e = f >> 3, c4 = f & 7;
            float4 v = __ldg(reinterpret_cast<const float4*>(
                W + (size_t)e * DD + kt * 32 + c4 * 4));
            ws2[c4 * 4 + 0][2 * e] = v.x; ws2[c4 * 4 + 0][2 * e + 1] = v.x;
            ws2[c4 * 4 + 1][2 * e] = v.y; ws2[c4 * 4 + 1][2 * e + 1] = v.y;
            ws2[c4 * 4 + 2][2 * e] = v.z; ws2[c4 * 4 + 2][2 * e + 1] = v.z;
            ws2[c4 * 4 + 3][2 * e] = v.w; ws2[c4 * 4 + 3][2 * e + 1] = v.w;
        }
        __syncthreads();

        unsigned long long acct[2][4] = {};  // fresh tile accumulator
        #pragma unroll 4
        for (int k = 0; k < 32; ++k) {
            unsigned long long wd[4], xp[2];
            #pragma unroll
            for (int j = 0; j < 4; ++j)
                wd[j] = *reinterpret_cast<const unsigned long long*>(&ws2[k][2 * (te * 4 + j)]);
            #pragma unroll
            for (int i = 0; i < 2; ++i)
                xp[i] = *reinterpret_cast<const unsigned long long*>(&xs[k][2 * tt + 32 * i]);
            #pragma unroll
            for (int i = 0; i < 2; ++i)
                #pragma unroll
                for (int j = 0; j < 4; ++j)
                    asm("fma.rn.f32x2 %0, %1, %2, %0;"
                        : "+l"(acct[i][j]) : "l"(xp[i]), "l"(wd[j]));
        }
        #pragma unroll
        for (int i = 0; i < 2; ++i)
            #pragma unroll
            for (int j = 0; j < 4; ++j)
                asm("add.rn.f32x2 %0, %0, %1;" : "+l"(accm[i][j]) : "l"(acct[i][j]));
    }
    __syncthreads();

    // spill logits to smem [tok][e]; acc lo-half = even token, hi-half = odd
    #pragma unroll
    for (int i = 0; i < 2; ++i)
        #pragma unroll
        for (int j = 0; j < 4; ++j) {
            int tok = 2 * tt + 32 * i, e = te * 4 + j;
            ls[tok + 0][e] = __uint_as_float((unsigned)(accm[i][j] & 0xffffffffu));
            ls[tok + 1][e] = __uint_as_float((unsigned)(accm[i][j] >> 32));
        }
    __syncthreads();

    // softmax: one thread per token (threads 0..63)
    if (tid < 64) {
        const int t = tid;
        float m = -1e30f;
        #pragma unroll
        for (int e = 0; e < EE; ++e) m = fmaxf(m, ls[t][e]);
        float s = 0.f;
        #pragma unroll
        for (int e = 0; e < EE; ++e) { float v = expf(ls[t][e] - m); ls[t][e] = v; s += v; }
        sinv[t] = 1.0f / s;
    }
    __syncthreads();

    // transposed coalesced write: probsT[b][e][n0+tok]
    const int b = m0 >> 12, n0 = m0 & (NN - 1);
    #pragma unroll
    for (int it = 0; it < 16; ++it) {
        int f = tid + it * 256;
        int e = f >> 6, tok = f & 63;
        g_probsT[b][e][n0 + tok] = ls[tok][e] * sinv[tok];
    }
}

// ============================================================================
// Kernel 2: per (batch, expert) descending bitonic sort of 4096 tokens by prob.
// key = prob_bits<<32 | (4095 - tok): probs > 0 -> uint-monotone; tie-break
// favors the lower token index, matching jax.lax.top_k.
// 1024 threads: 4 strided compare-exchanges between barriers.
// ============================================================================
__global__ void __launch_bounds__(1024) k_sort()
{
    __shared__ unsigned long long sk[NN];  // 32 KB
    const int b = blockIdx.x >> 6;
    const int e = blockIdx.x & 63;
    const int tid = threadIdx.x;
    const float* __restrict__ col = g_probsT[b][e];

    #pragma unroll
    for (int it = 0; it < NN / 1024; ++it) {
        int r = tid + it * 1024;
        unsigned pb = __float_as_uint(col[r]);
        sk[r] = ((unsigned long long)pb << 32) | (unsigned)(NN - 1 - r);
    }
    __syncthreads();

    for (int k2 = 2; k2 <= NN; k2 <<= 1) {
        for (int j = k2 >> 1; j > 0; j >>= 1) {
            #pragma unroll
            for (int it = 0; it < NN / 1024; ++it) {
                int i = tid + it * 1024;
                int ixj = i ^ j;
                if (ixj > i) {
                    bool asc = (i & k2) != 0;
                    unsigned long long a = sk[i], c = sk[ixj];
                    bool sw = asc ? (a > c) : (a < c);
                    if (sw) { sk[i] = c; sk[ixj] = a; }
                }
            }
            __syncthreads();
        }
    }
    #pragma unroll
    for (int it = 0; it < NN / 1024; ++it) {
        int r = tid + it * 1024;
        g_sorted[b][e][r] = (unsigned short)(NN - 1u - (unsigned)(sk[r] & 0xffffffffu));
    }
}

// ============================================================================
// Kernel 3: greedy expert-preferred assignment + output.
// One CTA per batch; experts j = E-1..0 take their top-kj unmasked tokens
// (block ballot + prefix walk over the presorted list). Next expert's first
// chunk is prefetched to hide the per-expert load latency.
// Output: [ M as float32 (B*N) | M_probs float32 (B*N) ]
// ============================================================================
__global__ void __launch_bounds__(512) k_greedy(const float* __restrict__ c,
                                                float* __restrict__ out)
{
    const int b = blockIdx.x;
    const int tid = threadIdx.x;
    __shared__ unsigned      maskw[NN / 32];  // chosen-token bitset
    __shared__ unsigned char sM[NN];
    __shared__ int   wsum[16];
    __shared__ float sc[EE];

    for (int i = tid; i < NN / 32; i += 512) maskw[i] = 0u;
    for (int i = tid; i < NN; i += 512) sM[i] = 0;
    if (tid < EE) sc[tid] = c[tid];
    __syncthreads();

    const int lane = tid & 31, wrp = tid >> 5;
    int tok = (int)g_sorted[b][EE - 1][tid];  // prefetch first expert's chunk 0

    for (int j = EE - 1; j >= 0; --j) {
        int pre = (j > 0) ? (int)g_sorted[b][j - 1][tid] : 0;  // prefetch next expert
        int kj = (int)floorf(sc[j] * (float)NN);
        if (kj > NN) kj = NN;
        int need = kj;
        int pos = 0;
        int cur = tok;
        while (need > 0 && pos < NN) {
            if (pos > 0) {
                int idx = pos + tid;
                cur = (idx < NN) ? (int)g_sorted[b][j][idx] : 0;
            }
            int valid = 0;
            if (pos + tid < NN)
                valid = ((maskw[cur >> 5] >> (cur & 31)) & 1u) ^ 1u;
            unsigned bal = __ballot_sync(0xffffffffu, valid);
            int lp = __popc(bal & ((1u << lane) - 1u));
            if (lane == 0) wsum[wrp] = __popc(bal);
            __syncthreads();
            int base = 0, total = 0;
            #pragma unroll
            for (int w = 0; w < 16; ++w) { int s = wsum[w]; if (w < wrp) base += s; total += s; }
            if (valid && (base + lp) < need) {
                sM[cur] = (unsigned char)j;
                atomicOr(&maskw[cur >> 5], 1u << (cur & 31));
            }
            need -= (total < need ? total : need);
            pos += 512;
            __syncthreads();
        }
        tok = pre;
    }

    // outputs: M (as float), then M_probs
    for (int t = tid; t < NN; t += 512) {
        int j = sM[t];
        out[(size_t)b * NN + t] = (float)j;
        out[(size_t)BN + (size_t)b * NN + t] = g_probsT[b][j][t];
    }
}

// ============================================================================
extern "C" void kernel_launch(void* const* d_in, const int* in_sizes, int n_in,
                              void* d_out, int out_size)
{
    const float* x = (const float*)d_in[0];   // [B, N, D]
    const float* W = (const float*)d_in[1];   // [E, D]
    const float* c = (const float*)d_in[2];   // [E]
    float* out = (float*)d_out;

    k_router_gemm<<<BN / 64, 256>>>(x, W);
    k_sort<<<BB * EE, 1024>>>();
    k_greedy<<<BB, 512>>>(c, out);
}

// round 14
// speedup vs baseline: 1.2823x; 1.2823x over previous
#include <cuda_runtime.h>
#include <cstdint>

// Problem shape (fixed by the dataset)
#define BB 4
#define NN 4096
#define DD 4096
#define EE 64
#define BN (BB * NN)
#define NQ 4            // K split factor
#define KQ (DD / NQ)    // 1024 k per quarter

// ---- scratch (no allocations allowed) ----
__device__ float          g_part[NQ][BN][EE];     // 16 MB: partial logits per K-quarter
__device__ float          g_probsT[BB][EE][NN];   // 4 MB: probs transposed [b][e][n]
__device__ unsigned short g_sorted[BB][EE][NN];   // 2 MB: per (b,e) token order, descending prob

// ============================================================================
// Kernel 1: router GEMM, K-split-4. 512 CTAs x 256 threads; CTA (tile, q)
// computes 128 tokens x 64 experts over K quarter = 1024.
// Thread mapping (verified: 256 thr x 32 outputs = 8192 = 128x64 tile):
//   tt = tid&15  -> token pairs {2tt, 2tt+1} + 32p, p in [0,4)
//   te = tid>>4  -> experts te*4 .. te*4+3   (te in [0,16))
// Per k: 4 LDS.64(x pairs) + 4 LDS.32(w) + 4 mov-dup + 16 FFMA2 (fma-bound).
// Two-level accumulation (per-32k tile folded into main) keeps fp32 noise
// ~4e-7 so the greedy ranking matches the reference.
// ============================================================================
__global__ void __launch_bounds__(256, 2) k_gemm_q(const float* __restrict__ x,
                                                   const float* __restrict__ W)
{
    __shared__ __align__(16) float su[6272];
    float (*xs)[130] = reinterpret_cast<float (*)[130]>(su);          // [k][tok], even stride -> LDS64 ok
    float (*ws)[66]  = reinterpret_cast<float (*)[66]>(su + 4160);    // [k][e]

    const int tid  = threadIdx.x;
    const int tt   = tid & 15;   // token-pair group
    const int te   = tid >> 4;   // expert group: experts te*4 .. te*4+3
    const int tile = blockIdx.x >> 2;
    const int q    = blockIdx.x & 3;
    const int m0   = tile * 128;
    const int k0   = q * KQ;

    unsigned long long accm[4][4] = {};  // [pair p][expert j], f32x2 = (tok even, tok odd)

    for (int kt = 0; kt < KQ / 32; ++kt) {   // 32 tiles of 32 k
        __syncthreads();
        // x tile: 128 tok x 32 k (float4 along k, transposed scalar stores)
        #pragma unroll
        for (int it = 0; it < 4; ++it) {
            int f = tid + it * 256;          // [0,1024)
            int r = f >> 3, c4 = f & 7;      // r<128, c4<8
            float4 v = __ldcs(reinterpret_cast<const float4*>(
                x + (size_t)(m0 + r) * DD + k0 + kt * 32 + c4 * 4));
            xs[c4 * 4 + 0][r] = v.x; xs[c4 * 4 + 1][r] = v.y;
            xs[c4 * 4 + 2][r] = v.z; xs[c4 * 4 + 3][r] = v.w;
        }
        // W tile: 64 e x 32 k
        #pragma unroll
        for (int it = 0; it < 2; ++it) {
            int f = tid + it * 256;          // [0,512)
            int e = f >> 3, c4 = f & 7;      // e<64
            float4 v = __ldg(reinterpret_cast<const float4*>(
                W + (size_t)e * DD + k0 + kt * 32 + c4 * 4));
            ws[c4 * 4 + 0][e] = v.x; ws[c4 * 4 + 1][e] = v.y;
            ws[c4 * 4 + 2][e] = v.z; ws[c4 * 4 + 3][e] = v.w;
        }
        __syncthreads();

        unsigned long long acct[4][4] = {};  // fresh per-tile accumulator
        #pragma unroll 4
        for (int k = 0; k < 32; ++k) {
            unsigned long long wd[4], xp[4];
            #pragma unroll
            for (int j = 0; j < 4; ++j) {
                unsigned wu = __float_as_uint(ws[k][te * 4 + j]);   // <=63 < 66 OK
                asm("mov.b64 %0, {%1, %1};" : "=l"(wd[j]) : "r"(wu));
            }
            #pragma unroll
            for (int p = 0; p < 4; ++p)      // tokens 2tt+32p, +1  (<=127 < 130 OK)
                xp[p] = *reinterpret_cast<const unsigned long long*>(&xs[k][2 * tt + 32 * p]);
            #pragma unroll
            for (int p = 0; p < 4; ++p)
                #pragma unroll
                for (int j = 0; j < 4; ++j)
                    asm("fma.rn.f32x2 %0, %1, %2, %0;"
                        : "+l"(acct[p][j]) : "l"(xp[p]), "l"(wd[j]));
        }
        #pragma unroll
        for (int p = 0; p < 4; ++p)
            #pragma unroll
            for (int j = 0; j < 4; ++j)
                asm("add.rn.f32x2 %0, %0, %1;" : "+l"(accm[p][j]) : "l"(acct[p][j]));
    }

    // epilogue: scalar stores (pair spans two token rows); 32 STG.32, amortized
    #pragma unroll
    for (int p = 0; p < 4; ++p)
        #pragma unroll
        for (int j = 0; j < 4; ++j) {
            int tok = m0 + 2 * tt + 32 * p;
            int e   = te * 4 + j;
            g_part[q][tok + 0][e] = __uint_as_float((unsigned)(accm[p][j] & 0xffffffffu));
            g_part[q][tok + 1][e] = __uint_as_float((unsigned)(accm[p][j] >> 32));
        }
}

// ============================================================================
// Kernel 1b: combine quarters (fixed order -> deterministic) + softmax +
// transposed write to probsT. 128 CTAs x 256 threads, 128 tokens each.
// ============================================================================
__global__ void __launch_bounds__(256) k_softmax()
{
    __shared__ float ls[128][65];
    __shared__ float sinv[128];
    const int tid = threadIdx.x;
    const int m0  = blockIdx.x * 128;
    const float* __restrict__ p0 = &g_part[0][m0][0];
    const float* __restrict__ p1 = &g_part[1][m0][0];
    const float* __restrict__ p2 = &g_part[2][m0][0];
    const float* __restrict__ p3 = &g_part[3][m0][0];

    #pragma unroll
    for (int it = 0; it < 32; ++it) {
        int f = tid + it * 256;                 // 0..8191, coalesced over [tok][e]
        ls[f >> 6][f & 63] = (p0[f] + p1[f]) + (p2[f] + p3[f]);
    }
    __syncthreads();

    if (tid < 128) {
        const int t = tid;
        float m = -1e30f;
        #pragma unroll
        for (int e = 0; e < EE; ++e) m = fmaxf(m, ls[t][e]);
        float s = 0.f;
        #pragma unroll
        for (int e = 0; e < EE; ++e) { float v = expf(ls[t][e] - m); ls[t][e] = v; s += v; }
        sinv[t] = 1.0f / s;
    }
    __syncthreads();

    const int b = m0 >> 12, n0 = m0 & (NN - 1);
    #pragma unroll
    for (int it = 0; it < 32; ++it) {
        int f = tid + it * 256;
        int e = f >> 7, tok = f & 127;
        g_probsT[b][e][n0 + tok] = ls[tok][e] * sinv[tok];
    }
}

// ============================================================================
// Kernel 2: per (batch, expert) descending bitonic sort of 4096 tokens by prob.
// key = prob_bits<<32 | (4095 - tok): probs > 0 -> uint-monotone; tie-break
// favors the lower token index, matching jax.lax.top_k.
// ============================================================================
__global__ void __launch_bounds__(1024) k_sort()
{
    __shared__ unsigned long long sk[NN];  // 32 KB
    const int b = blockIdx.x >> 6;
    const int e = blockIdx.x & 63;
    const int tid = threadIdx.x;
    const float* __restrict__ col = g_probsT[b][e];

    #pragma unroll
    for (int it = 0; it < NN / 1024; ++it) {
        int r = tid + it * 1024;
        unsigned pb = __float_as_uint(col[r]);
        sk[r] = ((unsigned long long)pb << 32) | (unsigned)(NN - 1 - r);
    }
    __syncthreads();

    for (int k2 = 2; k2 <= NN; k2 <<= 1) {
        for (int j = k2 >> 1; j > 0; j >>= 1) {
            #pragma unroll
            for (int it = 0; it < NN / 1024; ++it) {
                int i = tid + it * 1024;
                int ixj = i ^ j;
                if (ixj > i) {
                    bool asc = (i & k2) != 0;
                    unsigned long long a = sk[i], c = sk[ixj];
                    bool sw = asc ? (a > c) : (a < c);
                    if (sw) { sk[i] = c; sk[ixj] = a; }
                }
            }
            __syncthreads();
        }
    }
    #pragma unroll
    for (int it = 0; it < NN / 1024; ++it) {
        int r = tid + it * 1024;
        g_sorted[b][e][r] = (unsigned short)(NN - 1u - (unsigned)(sk[r] & 0xffffffffu));
    }
}

// ============================================================================
// Kernel 3: greedy expert-preferred assignment + output.
// One CTA per batch; experts j = E-1..0 take their top-kj unmasked tokens
// (block ballot + prefix walk over the presorted list).
// Output: [ M as float32 (B*N) | M_probs float32 (B*N) ]
// ============================================================================
__global__ void __launch_bounds__(512) k_greedy(const float* __restrict__ c,
                                                float* __restrict__ out)
{
    const int b = blockIdx.x;
    const int tid = threadIdx.x;
    __shared__ unsigned      maskw[NN / 32];  // chosen-token bitset
    __shared__ unsigned char sM[NN];
    __shared__ int   wsum[16];
    __shared__ float sc[EE];

    for (int i = tid; i < NN / 32; i += 512) maskw[i] = 0u;
    for (int i = tid; i < NN; i += 512) sM[i] = 0;
    if (tid < EE) sc[tid] = c[tid];
    __syncthreads();

    const int lane = tid & 31, wrp = tid >> 5;
    int tok = (int)g_sorted[b][EE - 1][tid];  // prefetch first expert's chunk 0

    for (int j = EE - 1; j >= 0; --j) {
        int pre = (j > 0) ? (int)g_sorted[b][j - 1][tid] : 0;  // prefetch next expert
        int kj = (int)floorf(sc[j] * (float)NN);
        if (kj > NN) kj = NN;
        int need = kj;
        int pos = 0;
        int cur = tok;
        while (need > 0 && pos < NN) {
            if (pos > 0) {
                int idx = pos + tid;
                cur = (idx < NN) ? (int)g_sorted[b][j][idx] : 0;
            }
            int valid = 0;
            if (pos + tid < NN)
                valid = ((maskw[cur >> 5] >> (cur & 31)) & 1u) ^ 1u;
            unsigned bal = __ballot_sync(0xffffffffu, valid);
            int lp = __popc(bal & ((1u << lane) - 1u));
            if (lane == 0) wsum[wrp] = __popc(bal);
            __syncthreads();
            int base = 0, total = 0;
            #pragma unroll
            for (int w = 0; w < 16; ++w) { int s = wsum[w]; if (w < wrp) base += s; total += s; }
            if (valid && (base + lp) < need) {
                sM[cur] = (unsigned char)j;
                atomicOr(&maskw[cur >> 5], 1u << (cur & 31));
            }
            need -= (total < need ? total : need);
            pos += 512;
            __syncthreads();
        }
        tok = pre;
    }

    // outputs: M (as float), then M_probs
    for (int t = tid; t < NN; t += 512) {
        int j = sM[t];
        out[(size_t)b * NN + t] = (float)j;
        out[(size_t)BN + (size_t)b * NN + t] = g_probsT[b][j][t];
    }
}

// ============================================================================
extern "C" void kernel_launch(void* const* d_in, const int* in_sizes, int n_in,
                              void* d_out, int out_size)
{
    const float* x = (const float*)d_in[0];   // [B, N, D]
    const float* W = (const float*)d_in[1];   // [E, D]
    const float* c = (const float*)d_in[2];   // [E]
    float* out = (float*)d_out;

    k_gemm_q<<<128 * NQ, 256>>>(x, W);
    k_softmax<<<128, 256>>>();
    k_sort<<<BB * EE, 1024>>>();
    k_greedy<<<BB, 512>>>(c, out);
}

// round 15
// speedup vs baseline: 1.3478x; 1.0511x over previous
#include <cuda_runtime.h>
#include <cstdint>

// Problem shape (fixed by the dataset)
#define BB 4
#define NN 4096
#define DD 4096
#define EE 64
#define BN (BB * NN)
#define NQ 4            // K split factor
#define KQ (DD / NQ)    // 1024 k per quarter

// ---- scratch (no allocations allowed) ----
__device__ float          g_part[NQ][BN][EE];     // 16 MB: partial logits per K-quarter
__device__ float          g_probsT[BB][EE][NN];   // 4 MB: probs transposed [b][e][n]
__device__ unsigned short g_sorted[BB][EE][NN];   // 2 MB: per (b,e) token order, descending prob

// ============================================================================
// Kernel 1: router GEMM, K-split-4. 512 CTAs x 128 threads; CTA (tile, q)
// computes 128 tokens x 64 experts over K quarter = 1024, 4 CTAs/SM.
// Thread mapping (coverage: 128 thr x 64 outputs = 8192 = 128x64):
//   tt = tid&15 -> token pairs {2tt,2tt+1} + 32p, p in [0,4)   (8 tokens)
//   te = tid>>4 -> experts te*8 .. te*8+7                      (te in [0,8))
// W stored DUPLICATED in smem ({w,w} via STS.64) so the inner loop is pure
// LDS.64: per k = 4 LDS64(x pairs) + 8 LDS64(w dup) + 32 FFMA2.
// LSU 12 cyc/warp/k (170K/SM) < fma 227K/SM -> fma-bound, 25% LSU headroom.
// Single-level fp32 accumulation (validated at rel_err 1e-6 in earlier runs).
// ============================================================================
__global__ void __launch_bounds__(128, 4) k_gemm_q(const float* __restrict__ x,
                                                   const float* __restrict__ W)
{
    __shared__ __align__(16) float su[8320];
    float (*xs)[130]  = reinterpret_cast<float (*)[130]>(su);          // [k][tok]
    float (*ws2)[130] = reinterpret_cast<float (*)[130]>(su + 4160);   // [k][2e] duplicated

    const int tid  = threadIdx.x;
    const int tt   = tid & 15;   // token-pair group
    const int te   = tid >> 4;   // expert group: experts te*8 .. te*8+7
    const int tile = blockIdx.x >> 2;
    const int q    = blockIdx.x & 3;
    const int m0   = tile * 128;
    const int k0   = q * KQ;

    unsigned long long acc[4][8] = {};  // [pair p][expert j], f32x2 = (tok even, tok odd)

    for (int kt = 0; kt < KQ / 32; ++kt) {   // 32 tiles of 32 k
        __syncthreads();
        // x tile: 128 tok x 32 k (float4 along k, transposed scalar stores)
        #pragma unroll
        for (int it = 0; it < 8; ++it) {
            int f = tid + it * 128;          // [0,1024)
            int r = f >> 3, c4 = f & 7;      // r<128, c4<8
            float4 v = __ldcs(reinterpret_cast<const float4*>(
                x + (size_t)(m0 + r) * DD + k0 + kt * 32 + c4 * 4));
            xs[c4 * 4 + 0][r] = v.x; xs[c4 * 4 + 1][r] = v.y;
            xs[c4 * 4 + 2][r] = v.z; xs[c4 * 4 + 3][r] = v.w;
        }
        // W tile: 64 e x 32 k, stored duplicated via 8B stores ({w,w})
        #pragma unroll
        for (int it = 0; it < 4; ++it) {
            int f = tid + it * 128;          // [0,512)
            int e = f >> 3, c4 = f & 7;      // e<64
            float4 v = __ldg(reinterpret_cast<const float4*>(
                W + (size_t)e * DD + k0 + kt * 32 + c4 * 4));
            *reinterpret_cast<float2*>(&ws2[c4 * 4 + 0][2 * e]) = make_float2(v.x, v.x);
            *reinterpret_cast<float2*>(&ws2[c4 * 4 + 1][2 * e]) = make_float2(v.y, v.y);
            *reinterpret_cast<float2*>(&ws2[c4 * 4 + 2][2 * e]) = make_float2(v.z, v.z);
            *reinterpret_cast<float2*>(&ws2[c4 * 4 + 3][2 * e]) = make_float2(v.w, v.w);
        }
        __syncthreads();

        #pragma unroll 2
        for (int k = 0; k < 32; ++k) {
            unsigned long long wd[8], xp[4];
            #pragma unroll
            for (int j = 0; j < 8; ++j)      // col 2*(te*8+j)+1 <= 127 < 130 OK
                wd[j] = *reinterpret_cast<const unsigned long long*>(&ws2[k][2 * (te * 8 + j)]);
            #pragma unroll
            for (int p = 0; p < 4; ++p)      // col 2tt+32p+1 <= 127 < 130 OK
                xp[p] = *reinterpret_cast<const unsigned long long*>(&xs[k][2 * tt + 32 * p]);
            #pragma unroll
            for (int p = 0; p < 4; ++p)
                #pragma unroll
                for (int j = 0; j < 8; ++j)
                    asm("fma.rn.f32x2 %0, %1, %2, %0;"
                        : "+l"(acc[p][j]) : "l"(xp[p]), "l"(wd[j]));
        }
    }

    // epilogue: scalar stores (pair spans two token rows); 64 STG.32, amortized
    #pragma unroll
    for (int p = 0; p < 4; ++p)
        #pragma unroll
        for (int j = 0; j < 8; ++j) {
            int tok = m0 + 2 * tt + 32 * p;
            int e   = te * 8 + j;
            g_part[q][tok + 0][e] = __uint_as_float((unsigned)(acc[p][j] & 0xffffffffu));
            g_part[q][tok + 1][e] = __uint_as_float((unsigned)(acc[p][j] >> 32));
        }
}

// ============================================================================
// Kernel 1b: combine quarters (fixed order -> deterministic) + softmax +
// transposed write to probsT. 128 CTAs x 256 threads, 128 tokens each.
// ============================================================================
__global__ void __launch_bounds__(256) k_softmax()
{
    __shared__ float ls[128][65];
    __shared__ float sinv[128];
    const int tid = threadIdx.x;
    const int m0  = blockIdx.x * 128;
    const float* __restrict__ p0 = &g_part[0][m0][0];
    const float* __restrict__ p1 = &g_part[1][m0][0];
    const float* __restrict__ p2 = &g_part[2][m0][0];
    const float* __restrict__ p3 = &g_part[3][m0][0];

    #pragma unroll
    for (int it = 0; it < 32; ++it) {
        int f = tid + it * 256;                 // 0..8191, coalesced over [tok][e]
        ls[f >> 6][f & 63] = (p0[f] + p1[f]) + (p2[f] + p3[f]);
    }
    __syncthreads();

    if (tid < 128) {
        const int t = tid;
        float m = -1e30f;
        #pragma unroll
        for (int e = 0; e < EE; ++e) m = fmaxf(m, ls[t][e]);
        float s = 0.f;
        #pragma unroll
        for (int e = 0; e < EE; ++e) { float v = expf(ls[t][e] - m); ls[t][e] = v; s += v; }
        sinv[t] = 1.0f / s;
    }
    __syncthreads();

    const int b = m0 >> 12, n0 = m0 & (NN - 1);
    #pragma unroll
    for (int it = 0; it < 32; ++it) {
        int f = tid + it * 256;
        int e = f >> 7, tok = f & 127;
        g_probsT[b][e][n0 + tok] = ls[tok][e] * sinv[tok];
    }
}

// ============================================================================
// Kernel 2: per (batch, expert) descending bitonic sort of 4096 tokens by prob.
// key = prob_bits<<32 | (4095 - tok): probs > 0 -> uint-monotone; tie-break
// favors the lower token index, matching jax.lax.top_k.
// ============================================================================
__global__ void __launch_bounds__(1024) k_sort()
{
    __shared__ unsigned long long sk[NN];  // 32 KB
    const int b = blockIdx.x >> 6;
    const int e = blockIdx.x & 63;
    const int tid = threadIdx.x;
    const float* __restrict__ col = g_probsT[b][e];

    #pragma unroll
    for (int it = 0; it < NN / 1024; ++it) {
        int r = tid + it * 1024;
        unsigned pb = __float_as_uint(col[r]);
        sk[r] = ((unsigned long long)pb << 32) | (unsigned)(NN - 1 - r);
    }
    __syncthreads();

    for (int k2 = 2; k2 <= NN; k2 <<= 1) {
        for (int j = k2 >> 1; j > 0; j >>= 1) {
            #pragma unroll
            for (int it = 0; it < NN / 1024; ++it) {
                int i = tid + it * 1024;
                int ixj = i ^ j;
                if (ixj > i) {
                    bool asc = (i & k2) != 0;
                    unsigned long long a = sk[i], c = sk[ixj];
                    bool sw = asc ? (a > c) : (a < c);
                    if (sw) { sk[i] = c; sk[ixj] = a; }
                }
            }
            __syncthreads();
        }
    }
    #pragma unroll
    for (int it = 0; it < NN / 1024; ++it) {
        int r = tid + it * 1024;
        g_sorted[b][e][r] = (unsigned short)(NN - 1u - (unsigned)(sk[r] & 0xffffffffu));
    }
}

// ============================================================================
// Kernel 3: greedy expert-preferred assignment + output.
// One CTA per batch; experts j = E-1..0 take their top-kj unmasked tokens
// (block ballot + prefix walk over the presorted list).
// Output: [ M as float32 (B*N) | M_probs float32 (B*N) ]
// ============================================================================
__global__ void __launch_bounds__(512) k_greedy(const float* __restrict__ c,
                                                float* __restrict__ out)
{
    const int b = blockIdx.x;
    const int tid = threadIdx.x;
    __shared__ unsigned      maskw[NN / 32];  // chosen-token bitset
    __shared__ unsigned char sM[NN];
    __shared__ int   wsum[16];
    __shared__ float sc[EE];

    for (int i = tid; i < NN / 32; i += 512) maskw[i] = 0u;
    for (int i = tid; i < NN; i += 512) sM[i] = 0;
    if (tid < EE) sc[tid] = c[tid];
    __syncthreads();

    const int lane = tid & 31, wrp = tid >> 5;
    int tok = (int)g_sorted[b][EE - 1][tid];  // prefetch first expert's chunk 0

    for (int j = EE - 1; j >= 0; --j) {
        int pre = (j > 0) ? (int)g_sorted[b][j - 1][tid] : 0;  // prefetch next expert
        int kj = (int)floorf(sc[j] * (float)NN);
        if (kj > NN) kj = NN;
        int need = kj;
        int pos = 0;
        int cur = tok;
        while (need > 0 && pos < NN) {
            if (pos > 0) {
                int idx = pos + tid;
                cur = (idx < NN) ? (int)g_sorted[b][j][idx] : 0;
            }
            int valid = 0;
            if (pos + tid < NN)
                valid = ((maskw[cur >> 5] >> (cur & 31)) & 1u) ^ 1u;
            unsigned bal = __ballot_sync(0xffffffffu, valid);
            int lp = __popc(bal & ((1u << lane) - 1u));
            if (lane == 0) wsum[wrp] = __popc(bal);
            __syncthreads();
            int base = 0, total = 0;
            #pragma unroll
            for (int w = 0; w < 16; ++w) { int s = wsum[w]; if (w < wrp) base += s; total += s; }
            if (valid && (base + lp) < need) {
                sM[cur] = (unsigned char)j;
                atomicOr(&maskw[cur >> 5], 1u << (cur & 31));
            }
            need -= (total < need ? total : need);
            pos += 512;
            __syncthreads();
        }
        tok = pre;
    }

    // outputs: M (as float), then M_probs
    for (int t = tid; t < NN; t += 512) {
        int j = sM[t];
        out[(size_t)b * NN + t] = (float)j;
        out[(size_t)BN + (size_t)b * NN + t] = g_probsT[b][j][t];
    }
}

// ============================================================================
extern "C" void kernel_launch(void* const* d_in, const int* in_sizes, int n_in,
                              void* d_out, int out_size)
{
    const float* x = (const float*)d_in[0];   // [B, N, D]
    const float* W = (const float*)d_in[1];   // [E, D]
    const float* c = (const float*)d_in[2];   // [E]
    float* out = (float*)d_out;

    k_gemm_q<<<128 * NQ, 128>>>(x, W);
    k_softmax<<<128, 256>>>();
    k_sort<<<BB * EE, 1024>>>();
    k_greedy<<<BB, 512>>>(c, out);
}

// round 16
// speedup vs baseline: 1.5062x; 1.1176x over previous
#include <cuda_runtime.h>
#include <cstdint>

// Problem shape (fixed by the dataset)
#define BB 4
#define NN 4096
#define DD 4096
#define EE 64
#define BN (BB * NN)

// ---- scratch (no allocations allowed) ----
__device__ unsigned       g_WhiT[DD * EE];        // 1 MB: tf32(W) transposed [d][e]
__device__ unsigned       g_WloT[DD * EE];        // 1 MB: tf32 residual, transposed
__device__ float          g_probsT[BB][EE][NN];   // 4 MB: probs transposed [b][e][n]
__device__ unsigned short g_sorted[BB][EE][NN];   // 2 MB: per (b,e) token order, descending prob

// split fp32 -> tf32 hi + tf32 lo (x = hi + lo + O(2^-22 x); x-hi exact by Sterbenz)
__device__ __forceinline__ void split_tf32(float v, unsigned& hi, unsigned& lo)
{
    asm("cvt.rna.tf32.f32 %0, %1;" : "=r"(hi) : "f"(v));
    float r = v - __uint_as_float(hi);
    asm("cvt.rna.tf32.f32 %0, %1;" : "=r"(lo) : "f"(r));
}

__device__ __forceinline__ void mma_tf32(float* c, const unsigned* a, unsigned b0, unsigned b1)
{
    asm volatile(
        "mma.sync.aligned.m16n8k8.row.col.f32.tf32.tf32.f32 "
        "{%0,%1,%2,%3}, {%4,%5,%6,%7}, {%8,%9}, {%0,%1,%2,%3};"
        : "+f"(c[0]), "+f"(c[1]), "+f"(c[2]), "+f"(c[3])
        : "r"(a[0]), "r"(a[1]), "r"(a[2]), "r"(a[3]), "r"(b0), "r"(b1));
}

// ============================================================================
// Kernel 0: pre-split W into tf32 hi/lo, transposed to [d][e] (1 MB each).
// ============================================================================
__global__ void __launch_bounds__(256) k_wsplit(const float* __restrict__ W)
{
    int idx = blockIdx.x * 256 + threadIdx.x;          // idx over [e][d]
    if (idx < EE * DD) {
        int e = idx >> 12, d = idx & (DD - 1);
        unsigned hi, lo;
        split_tf32(W[idx], hi, lo);
        g_WhiT[d * EE + e] = hi;
        g_WloT[d * EE + e] = lo;
    }
}

// ============================================================================
// Kernel 1: router GEMM via 3-term TF32 mma (Xhi*Whi + Xhi*Wlo + Xlo*Whi),
// fused softmax epilogue. 256 CTAs x 128 thr (4 warps); CTA = 64 tokens x
// 64 experts, K-loop in tiles of 32. Fragment layout = PTX m16n8k8:
//   A(row): a0(g,tig) a1(g+8,tig) a2(g,tig+4) a3(g+8,tig+4)
//   B(col): b0(k=tig,n=g) b1(k=tig+4,n=g)
//   D:      c0(g,2tig) c1(g,2tig+1) c2(g+8,2tig) c3(g+8,2tig+1)
// smem pads audited conflict-free: xs stride 36 (banks 4g+tig distinct),
// W stride 72 (banks 8tig+g distinct).
// ============================================================================
__global__ void __launch_bounds__(128, 4) k_gemm(const float* __restrict__ x)
{
    __shared__ __align__(16) float su[64 * 36 + 2 * 32 * 72];   // 27.6 KB
    float    (*xs)[36]  = reinterpret_cast<float (*)[36]>(su);                  // [row][k]
    unsigned (*whi)[72] = reinterpret_cast<unsigned (*)[72]>(su + 64 * 36);     // [k][e]
    unsigned (*wlo)[72] = reinterpret_cast<unsigned (*)[72]>(su + 64 * 36 + 32 * 72);

    const int tid  = threadIdx.x;
    const int wrp  = tid >> 5;
    const int lane = tid & 31;
    const int g    = lane >> 2;       // 0..7
    const int tig  = lane & 3;        // 0..3
    const int m0   = blockIdx.x * 64;

    float acc[8][4];                  // [ntile][c0..c3]
    #pragma unroll
    for (int n = 0; n < 8; ++n)
        #pragma unroll
        for (int c = 0; c < 4; ++c) acc[n][c] = 0.f;

    for (int kt = 0; kt < DD / 32; ++kt) {
        __syncthreads();
        // x tile: 64 rows x 32 k fp32 (512 float4)
        #pragma unroll
        for (int it = 0; it < 4; ++it) {
            int f = tid + it * 128;               // [0,512)
            int r = f >> 3, c4 = f & 7;           // r<64
            float4 v = __ldcs(reinterpret_cast<const float4*>(
                x + (size_t)(m0 + r) * DD + kt * 32 + c4 * 4));
            *reinterpret_cast<float4*>(&xs[r][c4 * 4]) = v;   // (36r+4c)%4==0 -> 16B aligned
        }
        // W hi/lo tiles: 32 k x 64 e u32 (512 uint4 each)
        #pragma unroll
        for (int it = 0; it < 4; ++it) {
            int f = tid + it * 128;               // [0,512)
            int k = f >> 4, c = f & 15;           // k<32, 16 uint4 per row
            *reinterpret_cast<uint4*>(&whi[k][c * 4]) =
                *reinterpret_cast<const uint4*>(&g_WhiT[(size_t)(kt * 32 + k) * EE + c * 4]);
            *reinterpret_cast<uint4*>(&wlo[k][c * 4]) =
                *reinterpret_cast<const uint4*>(&g_WloT[(size_t)(kt * 32 + k) * EE + c * 4]);
        }
        __syncthreads();

        #pragma unroll
        for (int kc = 0; kc < 4; ++kc) {
            const int r0 = wrp * 16 + g;
            unsigned ahi[4], alo[4];
            split_tf32(xs[r0    ][kc * 8 + tig    ], ahi[0], alo[0]);
            split_tf32(xs[r0 + 8][kc * 8 + tig    ], ahi[1], alo[1]);
            split_tf32(xs[r0    ][kc * 8 + tig + 4], ahi[2], alo[2]);
            split_tf32(xs[r0 + 8][kc * 8 + tig + 4], ahi[3], alo[3]);
            #pragma unroll
            for (int nt = 0; nt < 8; ++nt) {
                unsigned bh0 = whi[kc * 8 + tig    ][nt * 8 + g];
                unsigned bh1 = whi[kc * 8 + tig + 4][nt * 8 + g];
                unsigned bl0 = wlo[kc * 8 + tig    ][nt * 8 + g];
                unsigned bl1 = wlo[kc * 8 + tig + 4][nt * 8 + g];
                mma_tf32(acc[nt], ahi, bh0, bh1);   // Xhi*Whi
                mma_tf32(acc[nt], ahi, bl0, bl1);   // Xhi*Wlo
                mma_tf32(acc[nt], alo, bh0, bh1);   // Xlo*Whi
            }
        }
    }

    // epilogue: logits -> smem [e][row], softmax per row, coalesced store
    __syncthreads();
    float (*ps)[65] = reinterpret_cast<float (*)[65]>(su);   // 64x65 = 16.6KB <= su
    #pragma unroll
    for (int nt = 0; nt < 8; ++nt) {
        int col = nt * 8 + 2 * tig, r0 = wrp * 16 + g;
        ps[col    ][r0    ] = acc[nt][0];
        ps[col + 1][r0    ] = acc[nt][1];
        ps[col    ][r0 + 8] = acc[nt][2];
        ps[col + 1][r0 + 8] = acc[nt][3];
    }
    __syncthreads();

    if (tid < 64) {
        const int t = tid;
        float m = -1e30f;
        #pragma unroll
        for (int e = 0; e < EE; ++e) m = fmaxf(m, ps[e][t]);
        float s = 0.f;
        #pragma unroll
        for (int e = 0; e < EE; ++e) { float v = expf(ps[e][t] - m); ps[e][t] = v; s += v; }
        float inv = 1.0f / s;
        #pragma unroll
        for (int e = 0; e < EE; ++e) ps[e][t] *= inv;
    }
    __syncthreads();

    const int b = m0 >> 12, n0 = m0 & (NN - 1);
    #pragma unroll
    for (int it = 0; it < 32; ++it) {
        int f = tid + it * 128;          // [0,4096)
        int e = f >> 6, r = f & 63;
        g_probsT[b][e][n0 + r] = ps[e][r];
    }
}

// ============================================================================
// Kernel 2: per (batch, expert) descending bitonic sort of 4096 tokens by prob.
// key = prob_bits<<32 | (4095 - tok): probs > 0 -> uint-monotone; tie-break
// favors the lower token index, matching jax.lax.top_k.
// ============================================================================
__global__ void __launch_bounds__(1024) k_sort()
{
    __shared__ unsigned long long sk[NN];  // 32 KB
    const int b = blockIdx.x >> 6;
    const int e = blockIdx.x & 63;
    const int tid = threadIdx.x;
    const float* __restrict__ col = g_probsT[b][e];

    #pragma unroll
    for (int it = 0; it < NN / 1024; ++it) {
        int r = tid + it * 1024;
        unsigned pb = __float_as_uint(col[r]);
        sk[r] = ((unsigned long long)pb << 32) | (unsigned)(NN - 1 - r);
    }
    __syncthreads();

    for (int k2 = 2; k2 <= NN; k2 <<= 1) {
        for (int j = k2 >> 1; j > 0; j >>= 1) {
            #pragma unroll
            for (int it = 0; it < NN / 1024; ++it) {
                int i = tid + it * 1024;
                int ixj = i ^ j;
                if (ixj > i) {
                    bool asc = (i & k2) != 0;
                    unsigned long long a = sk[i], c = sk[ixj];
                    bool sw = asc ? (a > c) : (a < c);
                    if (sw) { sk[i] = c; sk[ixj] = a; }
                }
            }
            __syncthreads();
        }
    }
    #pragma unroll
    for (int it = 0; it < NN / 1024; ++it) {
        int r = tid + it * 1024;
        g_sorted[b][e][r] = (unsigned short)(NN - 1u - (unsigned)(sk[r] & 0xffffffffu));
    }
}

// ============================================================================
// Kernel 3: greedy expert-preferred assignment + output.
// One CTA per batch; experts j = E-1..0 take their top-kj unmasked tokens
// (block ballot + prefix walk over the presorted list).
// Output: [ M as float32 (B*N) | M_probs float32 (B*N) ]
// ============================================================================
__global__ void __launch_bounds__(512) k_greedy(const float* __restrict__ c,
                                                float* __restrict__ out)
{
    const int b = blockIdx.x;
    const int tid = threadIdx.x;
    __shared__ unsigned      maskw[NN / 32];  // chosen-token bitset
    __shared__ unsigned char sM[NN];
    __shared__ int   wsum[16];
    __shared__ float sc[EE];

    for (int i = tid; i < NN / 32; i += 512) maskw[i] = 0u;
    for (int i = tid; i < NN; i += 512) sM[i] = 0;
    if (tid < EE) sc[tid] = c[tid];
    __syncthreads();

    const int lane = tid & 31, wrp = tid >> 5;
    int tok = (int)g_sorted[b][EE - 1][tid];  // prefetch first expert's chunk 0

    for (int j = EE - 1; j >= 0; --j) {
        int pre = (j > 0) ? (int)g_sorted[b][j - 1][tid] : 0;  // prefetch next expert
        int kj = (int)floorf(sc[j] * (float)NN);
        if (kj > NN) kj = NN;
        int need = kj;
        int pos = 0;
        int cur = tok;
        while (need > 0 && pos < NN) {
            if (pos > 0) {
                int idx = pos + tid;
                cur = (idx < NN) ? (int)g_sorted[b][j][idx] : 0;
            }
            int valid = 0;
            if (pos + tid < NN)
                valid = ((maskw[cur >> 5] >> (cur & 31)) & 1u) ^ 1u;
            unsigned bal = __ballot_sync(0xffffffffu, valid);
            int lp = __popc(bal & ((1u << lane) - 1u));
            if (lane == 0) wsum[wrp] = __popc(bal);
            __syncthreads();
            int base = 0, total = 0;
            #pragma unroll
            for (int w = 0; w < 16; ++w) { int s = wsum[w]; if (w < wrp) base += s; total += s; }
            if (valid && (base + lp) < need) {
                sM[cur] = (unsigned char)j;
                atomicOr(&maskw[cur >> 5], 1u << (cur & 31));
            }
            need -= (total < need ? total : need);
            pos += 512;
            __syncthreads();
        }
        tok = pre;
    }

    // outputs: M (as float), then M_probs
    for (int t = tid; t < NN; t += 512) {
        int j = sM[t];
        out[(size_t)b * NN + t] = (float)j;
        out[(size_t)BN + (size_t)b * NN + t] = g_probsT[b][j][t];
    }
}

// ============================================================================
extern "C" void kernel_launch(void* const* d_in, const int* in_sizes, int n_in,
                              void* d_out, int out_size)
{
    const float* x = (const float*)d_in[0];   // [B, N, D]
    const float* W = (const float*)d_in[1];   // [E, D]
    const float* c = (const float*)d_in[2];   // [E]
    float* out = (float*)d_out;

    k_wsplit<<<(EE * DD + 255) / 256, 256>>>(W);
    k_gemm<<<BN / 64, 128>>>(x);
    k_sort<<<BB * EE, 1024>>>();
    k_greedy<<<BB, 512>>>(c, out);
}